// round 16
// baseline (speedup 1.0000x reference)
#include <cuda_runtime.h>
#include <cuda_bf16.h>
#include <cstdint>

// ---------------- problem constants ----------------
#define BATCH    1024
#define NITEMS   100000
#define EMB      128
#define TOPK     50

// gemm1 tiling: 128 rows x 128 dims per block, K-split over items
#define SPLIT    125         // K-split over NITEMS
#define KC       800         // NITEMS / SPLIT
#define TI       16          // item chunk staged in smem
#define RB       128         // rows per block
#define SPAD     132         // smem row pad (floats)
#define NCHUNK   (KC / TI)   // 50

// gemm2 (tensor core) tiling
#define JTILE    128
#define RTILE    128
#define KCH      32
#define APAD     36

// topk
#define SAMPLE_U4   781      // uint4 samples per row (every 16th of 12500)
#define CAND_TARGET 64       // sampled suffix-count target
#define CAND_MAX    2048
#define QHALF       6250     // half of the 12500 uint4 per row

// ---------------- device scratch (static: no allocations) ----------------
__device__ float g_part[(size_t)SPLIT * BATCH * EMB];        // 65.5 MB
__device__ float g_xemb[BATCH * EMB];                        // 0.5 MB
__device__ __nv_bfloat16 g_scores[(size_t)BATCH * NITEMS];   // 204.8 MB

// ---------------- tf32 helpers ----------------
__device__ __forceinline__ uint32_t f2tf32(float f) {
    uint32_t u;
    asm("cvt.rna.tf32.f32 %0, %1;" : "=r"(u) : "f"(f));
    return u;
}
__device__ __forceinline__ void mma_tf32(float c[4],
                                         uint32_t a0, uint32_t a1, uint32_t a2, uint32_t a3,
                                         uint32_t b0, uint32_t b1) {
    asm("mma.sync.aligned.m16n8k8.row.col.f32.tf32.tf32.f32 "
        "{%0,%1,%2,%3}, {%4,%5,%6,%7}, {%8,%9}, {%0,%1,%2,%3};"
        : "+f"(c[0]), "+f"(c[1]), "+f"(c[2]), "+f"(c[3])
        : "r"(a0), "r"(a1), "r"(a2), "r"(a3), "r"(b0), "r"(b1));
}

// ---------------- kernel 1: x_emb partials = x @ E (fp32, K-split) -------------
// NUMERICS FROZEN (matches reference ranking; verified rel_err 0.0 twice).
// Double-buffered smem staging; per-thread FMA order bit-identical.
__global__ __launch_bounds__(256) void k_gemm1(const float* __restrict__ x,
                                               const float* __restrict__ E) {
    __shared__ float xs[2][TI][SPAD];   // [buf][item][row]
    __shared__ float Es[2][TI][SPAD];   // [buf][item][dim]
    const int tid  = threadIdx.x;
    const int rg   = tid >> 4;
    const int dg   = tid & 15;
    const int row0 = blockIdx.x * RB;
    const int i0   = blockIdx.y * KC;
    const int r0   = rg * 8;
    const int d0   = dg * 8;

    float gacc[8][8];
    #pragma unroll
    for (int r = 0; r < 8; r++)
        #pragma unroll
        for (int c = 0; c < 8; c++) gacc[r][c] = 0.f;

    auto stage = [&](int ic, int b) {
        for (int t = tid; t < RB * (TI / 4); t += 256) {
            int r  = t >> 2;
            int iv = t & 3;
            float4 v = *reinterpret_cast<const float4*>(
                &x[(size_t)(row0 + r) * NITEMS + i0 + ic + iv * 4]);
            xs[b][iv * 4 + 0][r] = v.x;
            xs[b][iv * 4 + 1][r] = v.y;
            xs[b][iv * 4 + 2][r] = v.z;
            xs[b][iv * 4 + 3][r] = v.w;
        }
        for (int t = tid; t < TI * (EMB / 4); t += 256) {
            int i  = t >> 5;
            int dq = t & 31;
            float4 v = *reinterpret_cast<const float4*>(
                &E[(size_t)(i0 + ic + i) * EMB + dq * 4]);
            *reinterpret_cast<float4*>(&Es[b][i][dq * 4]) = v;
        }
    };

    stage(0, 0);
    __syncthreads();

    for (int cch = 0; cch < NCHUNK; cch++) {
        const int b = cch & 1;
        if (cch + 1 < NCHUNK) stage((cch + 1) * TI, b ^ 1);

        float facc[8][8];
        #pragma unroll
        for (int r = 0; r < 8; r++)
            #pragma unroll
            for (int c = 0; c < 8; c++) facc[r][c] = 0.f;

        #pragma unroll
        for (int k = 0; k < TI; k++) {
            float4 xa = *reinterpret_cast<const float4*>(&xs[b][k][r0]);
            float4 xb = *reinterpret_cast<const float4*>(&xs[b][k][r0 + 4]);
            float4 ea = *reinterpret_cast<const float4*>(&Es[b][k][d0]);
            float4 eb = *reinterpret_cast<const float4*>(&Es[b][k][d0 + 4]);
            float xr[8] = {xa.x, xa.y, xa.z, xa.w, xb.x, xb.y, xb.z, xb.w};
            float ec[8] = {ea.x, ea.y, ea.z, ea.w, eb.x, eb.y, eb.z, eb.w};
            #pragma unroll
            for (int r = 0; r < 8; r++)
                #pragma unroll
                for (int c = 0; c < 8; c++)
                    facc[r][c] = fmaf(xr[r], ec[c], facc[r][c]);
        }
        #pragma unroll
        for (int r = 0; r < 8; r++)
            #pragma unroll
            for (int c = 0; c < 8; c++) gacc[r][c] += facc[r][c];

        __syncthreads();
    }

    float* part = &g_part[(size_t)blockIdx.y * BATCH * EMB];
    #pragma unroll
    for (int r = 0; r < 8; r++) {
        float* pp = &part[(size_t)(row0 + r0 + r) * EMB + d0];
        *reinterpret_cast<float4*>(pp) =
            make_float4(gacc[r][0], gacc[r][1], gacc[r][2], gacc[r][3]);
        *reinterpret_cast<float4*>(pp + 4) =
            make_float4(gacc[r][4], gacc[r][5], gacc[r][6], gacc[r][7]);
    }
}

// ---------------- kernel 1b: fold K-split partials in fp64 ----------------
__global__ __launch_bounds__(256) void k_reduce() {
    int i = blockIdx.x * blockDim.x + threadIdx.x;
    if (i < BATCH * EMB) {
        double sum = 0.0;
        for (int s = 0; s < SPLIT; s++) sum += (double)g_part[(size_t)s * BATCH * EMB + i];
        g_xemb[i] = (float)sum;
    }
}

// ---------------- kernel 2: scores = x_emb @ E^T (tf32 TC, bf16 output) --------
__global__ __launch_bounds__(256) void k_gemm2_tc(const float* __restrict__ E) {
    __shared__ uint32_t As[RTILE][APAD];
    __shared__ uint32_t Bs[JTILE][APAD];
    const int tid  = threadIdx.x;
    const int lane = tid & 31;
    const int warp = tid >> 5;
    const int row0 = blockIdx.y * RTILE;
    const int j0   = blockIdx.x * JTILE;
    const int g    = lane >> 2;
    const int c    = lane & 3;

    float cr[16][4];
    #pragma unroll
    for (int nt = 0; nt < 16; nt++)
        #pragma unroll
        for (int q = 0; q < 4; q++) cr[nt][q] = 0.f;

    for (int kc = 0; kc < EMB; kc += KCH) {
        __syncthreads();
        for (int t = tid; t < RTILE * (KCH / 4); t += 256) {
            int r  = t >> 3;
            int kq = t & 7;
            float4 v = *reinterpret_cast<const float4*>(
                &g_xemb[(size_t)(row0 + r) * EMB + kc + kq * 4]);
            uint4 u = make_uint4(f2tf32(v.x), f2tf32(v.y), f2tf32(v.z), f2tf32(v.w));
            *reinterpret_cast<uint4*>(&As[r][kq * 4]) = u;
        }
        for (int t = tid; t < JTILE * (KCH / 4); t += 256) {
            int r  = t >> 3;
            int kq = t & 7;
            int jj = j0 + r;
            if (jj >= NITEMS) jj = NITEMS - 1;
            float4 v = *reinterpret_cast<const float4*>(
                &E[(size_t)jj * EMB + kc + kq * 4]);
            uint4 u = make_uint4(f2tf32(v.x), f2tf32(v.y), f2tf32(v.z), f2tf32(v.w));
            *reinterpret_cast<uint4*>(&Bs[r][kq * 4]) = u;
        }
        __syncthreads();

        #pragma unroll
        for (int s = 0; s < KCH / 8; s++) {
            const int k0 = s * 8;
            uint32_t a0 = As[warp * 16 + g][k0 + c];
            uint32_t a1 = As[warp * 16 + 8 + g][k0 + c];
            uint32_t a2 = As[warp * 16 + g][k0 + c + 4];
            uint32_t a3 = As[warp * 16 + 8 + g][k0 + c + 4];
            #pragma unroll
            for (int nt = 0; nt < 16; nt++) {
                uint32_t b0 = Bs[nt * 8 + g][k0 + c];
                uint32_t b1 = Bs[nt * 8 + g][k0 + c + 4];
                mma_tf32(cr[nt], a0, a1, a2, a3, b0, b1);
            }
        }
    }

    #pragma unroll
    for (int nt = 0; nt < 16; nt++) {
        if (j0 + nt * 8 + 8 <= NITEMS) {
            int jz = j0 + nt * 8 + 2 * c;
            int r  = row0 + warp * 16 + g;
            __nv_bfloat162 p01 = make_bfloat162(__float2bfloat16_rn(cr[nt][0]),
                                                __float2bfloat16_rn(cr[nt][1]));
            __nv_bfloat162 p23 = make_bfloat162(__float2bfloat16_rn(cr[nt][2]),
                                                __float2bfloat16_rn(cr[nt][3]));
            *reinterpret_cast<__nv_bfloat162*>(&g_scores[(size_t)r * NITEMS + jz]) = p01;
            *reinterpret_cast<__nv_bfloat162*>(&g_scores[(size_t)(r + 8) * NITEMS + jz]) = p23;
        }
    }
}

// ---------------- kernel 3: sampled thresh + overflow-safe compact + fp64 -------
__device__ __forceinline__ unsigned ord16(unsigned h) {   // ordered bf16 (16-bit)
    return (h & 0x8000u) ? (0xffffu & ~h) : (h | 0x8000u);
}
__device__ __forceinline__ unsigned long long ordu64(double d) {
    unsigned long long u = __double_as_longlong(d);
    return (u & 0x8000000000000000ull) ? ~u : (u | 0x8000000000000000ull);
}

__global__ __launch_bounds__(256) void k_topk(const float* __restrict__ E,
                                              float* __restrict__ out) {
    __shared__ union {
        unsigned hist[4096];
        unsigned long long keys[CAND_MAX];
    } u;
    __shared__ unsigned cidx[CAND_MAX];
    __shared__ float xrow[EMB];
    __shared__ unsigned strip[256];
    __shared__ int s_bin, s_cnt;
    __shared__ unsigned long long wkey[8];
    __shared__ unsigned wbi[8];
    __shared__ int wpos[8];

    const int row = blockIdx.x;
    const int tid = threadIdx.x;
    const int lane = tid & 31;
    const int warp = tid >> 5;
    const uint4* s16 = reinterpret_cast<const uint4*>(&g_scores[(size_t)row * NITEMS]);

    if (tid < EMB) xrow[tid] = g_xemb[row * EMB + tid];
    for (int b = tid; b < 4096; b += 256) u.hist[b] = 0;
    __syncthreads();

    // pass 1 (SAMPLED): histogram every 16th uint4 (6248 of 100000 bf16).
    for (int i = tid; i < SAMPLE_U4; i += 256) {
        uint4 v = s16[i * 16];
        unsigned w[4] = {v.x, v.y, v.z, v.w};
        #pragma unroll
        for (int q = 0; q < 4; q++) {
            atomicAdd(&u.hist[ord16(w[q] & 0xffffu) >> 4], 1u);
            atomicAdd(&u.hist[ord16(w[q] >> 16) >> 4], 1u);
        }
    }
    __syncthreads();

    // suffix scan for bin with sampled above-count < CAND_TARGET <= inclusive.
    // Guarantees full count >= CAND_TARGET >= TOPK (sample is a subset).
    unsigned loc = 0;
    #pragma unroll
    for (int q = 0; q < 16; q++) loc += u.hist[tid * 16 + q];
    strip[tid] = loc;
    __syncthreads();
    if (tid == 0) {
        int acc = 0, bin = 0;
        for (int t = 255; t >= 0; t--) {
            if (acc + (int)strip[t] >= CAND_TARGET) {
                for (int b = t * 16 + 15; b >= t * 16; b--) {
                    if (acc + (int)u.hist[b] >= CAND_TARGET) { bin = b; break; }
                    acc += (int)u.hist[b];
                }
                break;
            }
            acc += (int)strip[t];
        }
        s_bin = bin;
    }
    __syncthreads();

    // pass 2 (FULL) with OVERFLOW-SAFE retry: raise threshold one bin and
    // re-compact while the candidate count exceeds CAND_MAX. Sampled estimate
    // has percent-level P(count > CAND_MAX); truncation there silently drops
    // true top-50 members (the round-14 failure). Retry cost: one extra
    // streaming pass on the rare affected rows.
    int bin = s_bin;
    int cnt;
    for (int attempt = 0; attempt < 16; attempt++) {
        if (tid == 0) s_cnt = 0;
        __syncthreads();
        const unsigned thresh = ((unsigned)bin) << 4;
        for (int i = tid; i < QHALF; i += 256) {
            uint4 va = s16[i];
            uint4 vb = s16[i + QHALF];
            unsigned w[8] = {va.x, va.y, va.z, va.w, vb.x, vb.y, vb.z, vb.w};
            #pragma unroll
            for (int q = 0; q < 8; q++) {
                int base = (q < 4) ? (8 * i + 2 * q) : (8 * (i + QHALF) + 2 * (q - 4));
                if (ord16(w[q] & 0xffffu) >= thresh) {
                    int p = atomicAdd(&s_cnt, 1);
                    if (p < CAND_MAX) cidx[p] = (unsigned)base;
                }
                if (ord16(w[q] >> 16) >= thresh) {
                    int p = atomicAdd(&s_cnt, 1);
                    if (p < CAND_MAX) cidx[p] = (unsigned)(base + 1);
                }
            }
        }
        __syncthreads();
        cnt = s_cnt;                      // uniform
        if (cnt <= CAND_MAX) break;       // fits: candidate set is complete
        if (bin >= 4095) break;           // cannot raise further (pathological)
        bin++;                            // too many: raise threshold, retry
        __syncthreads();
    }
    if (cnt > CAND_MAX) cnt = CAND_MAX;   // pathological-only truncation

    if (cnt < TOPK) {   // fail-safe, unreachable on healthy data
        for (int i = tid; i < CAND_MAX; i += 256) cidx[i] = (unsigned)i;
        cnt = CAND_MAX;
        __syncthreads();
    }

    __syncthreads();   // hist reads done; safe to alias u.keys
    // fp64 rescore: one warp per candidate; lane owns 4 dims
    for (int c2 = warp; c2 < cnt; c2 += 8) {
        const unsigned j = cidx[c2];
        const float4* Ej4 = reinterpret_cast<const float4*>(&E[(size_t)j * EMB]);
        float4 ev = __ldg(&Ej4[lane]);
        float4 xv = *reinterpret_cast<const float4*>(&xrow[lane * 4]);
        double s = (double)xv.x * (double)ev.x + (double)xv.y * (double)ev.y
                 + (double)xv.z * (double)ev.z + (double)xv.w * (double)ev.w;
        #pragma unroll
        for (int off = 16; off; off >>= 1)
            s += __shfl_down_sync(0xffffffffu, s, off);
        if (lane == 0) u.keys[c2] = ordu64(s);
    }
    __syncthreads();

    // 50 selections: fp64 value desc, item index asc on ties
    for (int k = 0; k < TOPK; k++) {
        unsigned long long bk = 0; unsigned bi = 0xffffffffu; int bp = -1;
        for (int i = tid; i < cnt; i += 256) {
            unsigned long long kk = u.keys[i];
            unsigned ii = cidx[i];
            if (kk > bk || (kk == bk && ii < bi)) { bk = kk; bi = ii; bp = i; }
        }
        #pragma unroll
        for (int off = 16; off; off >>= 1) {
            unsigned long long ok = __shfl_down_sync(0xffffffffu, bk, off);
            unsigned oi = __shfl_down_sync(0xffffffffu, bi, off);
            int op = __shfl_down_sync(0xffffffffu, bp, off);
            if (ok > bk || (ok == bk && oi < bi)) { bk = ok; bi = oi; bp = op; }
        }
        if (lane == 0) { wkey[warp] = bk; wbi[warp] = bi; wpos[warp] = bp; }
        __syncthreads();
        if (tid == 0) {
            unsigned long long fb = 0; unsigned fi = 0xffffffffu; int fp = -1;
            #pragma unroll
            for (int w = 0; w < 8; w++)
                if (wkey[w] > fb || (wkey[w] == fb && wbi[w] < fi)) {
                    fb = wkey[w]; fi = wbi[w]; fp = wpos[w];
                }
            out[row * TOPK + k] = (float)fi;
            if (fp >= 0) u.keys[fp] = 0;
        }
        __syncthreads();
    }
}

// ---------------- launch ----------------
extern "C" void kernel_launch(void* const* d_in, const int* in_sizes, int n_in,
                              void* d_out, int out_size) {
    const float* a0 = (const float*)d_in[0];
    const float* a1 = (const float*)d_in[1];
    const bool first_is_x = (in_sizes[0] == BATCH * NITEMS) ||
                            (in_sizes[0] == BATCH * NITEMS * 4);
    const float* x = first_is_x ? a0 : a1;             // [1024, 100000]
    const float* E = first_is_x ? a1 : a0;             // [100000, 128]
    float* out = (float*)d_out;                        // [1024, 50] float32 indices

    k_gemm1<<<dim3(BATCH / RB, SPLIT), 256>>>(x, E);
    k_reduce<<<(BATCH * EMB + 255) / 256, 256>>>();
    k_gemm2_tc<<<dim3((NITEMS + JTILE - 1) / JTILE, BATCH / RTILE), 256>>>(E);
    k_topk<<<BATCH, 256>>>(E, out);
}

// round 17
// speedup vs baseline: 1.1254x; 1.1254x over previous
#include <cuda_runtime.h>
#include <cuda_bf16.h>
#include <cstdint>

// ---------------- problem constants ----------------
#define BATCH    1024
#define NITEMS   100000
#define EMB      128
#define TOPK     50

// gemm1 tiling: 128 rows x 128 dims per block, K-split over items
#define SPLIT    125         // K-split over NITEMS
#define KC       800         // NITEMS / SPLIT
#define TI       16          // item chunk staged in smem
#define RB       128         // rows per block
#define SPAD     132         // smem row pad (floats)
#define NCHUNK   (KC / TI)   // 50

// gemm2 (tensor core) tiling
#define JTILE    128
#define RTILE    128
#define KCH      32
#define APAD     36

// topk
#define SAMPLE_U4   781      // uint4 samples per row (every 16th of 12500)
#define CAND_TARGET 64       // sampled suffix-count target
#define CAND_MAX    2048
#define QHALF       6250     // half of the 12500 uint4 per row

// ---------------- device scratch (static: no allocations) ----------------
__device__ float g_part[(size_t)SPLIT * BATCH * EMB];        // 65.5 MB
__device__ float g_xemb[BATCH * EMB];                        // 0.5 MB
__device__ __nv_bfloat16 g_scores[(size_t)BATCH * NITEMS];   // 204.8 MB

// ---------------- tf32 helpers ----------------
__device__ __forceinline__ uint32_t f2tf32(float f) {
    uint32_t u;
    asm("cvt.rna.tf32.f32 %0, %1;" : "=r"(u) : "f"(f));
    return u;
}
__device__ __forceinline__ void mma_tf32(float c[4],
                                         uint32_t a0, uint32_t a1, uint32_t a2, uint32_t a3,
                                         uint32_t b0, uint32_t b1) {
    asm("mma.sync.aligned.m16n8k8.row.col.f32.tf32.tf32.f32 "
        "{%0,%1,%2,%3}, {%4,%5,%6,%7}, {%8,%9}, {%0,%1,%2,%3};"
        : "+f"(c[0]), "+f"(c[1]), "+f"(c[2]), "+f"(c[3])
        : "r"(a0), "r"(a1), "r"(a2), "r"(a3), "r"(b0), "r"(b1));
}

// ---------------- cp.async helpers (zero-register double buffering) ------------
__device__ __forceinline__ void cpa4(uint32_t smem_addr, const void* gptr) {
    asm volatile("cp.async.ca.shared.global [%0], [%1], 4;\n"
                 :: "r"(smem_addr), "l"(gptr));
}
__device__ __forceinline__ void cpa16(uint32_t smem_addr, const void* gptr) {
    asm volatile("cp.async.ca.shared.global [%0], [%1], 16;\n"
                 :: "r"(smem_addr), "l"(gptr));
}
__device__ __forceinline__ void cpa_commit() {
    asm volatile("cp.async.commit_group;\n");
}
template <int N>
__device__ __forceinline__ void cpa_wait() {
    asm volatile("cp.async.wait_group %0;\n" :: "n"(N));
}

// ---------------- kernel 1: x_emb partials = x @ E (fp32, K-split) -------------
// NUMERICS FROZEN: the compute loop (and hence per-thread FMA order) is
// bit-identical to the verified rel_err-0.0 version. This round changes ONLY
// the staging mechanism: cp.async double-buffer — same values into the same
// smem slots, zero extra registers (the round-16 register-double-buffer
// regression was a spill cliff: 128 accum regs + ~32 staging regs).
__global__ __launch_bounds__(256) void k_gemm1(const float* __restrict__ x,
                                               const float* __restrict__ E) {
    __shared__ float xs[2][TI][SPAD];   // [buf][item][row]
    __shared__ float Es[2][TI][SPAD];   // [buf][item][dim]
    const int tid  = threadIdx.x;
    const int rg   = tid >> 4;
    const int dg   = tid & 15;
    const int row0 = blockIdx.x * RB;
    const int i0   = blockIdx.y * KC;
    const int r0   = rg * 8;
    const int d0   = dg * 8;

    const uint32_t xs_base = (uint32_t)__cvta_generic_to_shared(&xs[0][0][0]);
    const uint32_t es_base = (uint32_t)__cvta_generic_to_shared(&Es[0][0][0]);

    float gacc[8][8];
    #pragma unroll
    for (int r = 0; r < 8; r++)
        #pragma unroll
        for (int c = 0; c < 8; c++) gacc[r][c] = 0.f;

    // async-stage chunk `ic` into buffer `b`; commits one cp.async group
    auto stage_async = [&](int ic, int b) {
        // x chunk [128 rows][16 items], transposed into xs[b][i][r]: 4B copies
        for (int t = tid; t < RB * (TI / 4); t += 256) {
            int r  = t >> 2;
            int iv = t & 3;
            const float* gp = &x[(size_t)(row0 + r) * NITEMS + i0 + ic + iv * 4];
            uint32_t sa = xs_base + (uint32_t)(((b * TI + iv * 4) * SPAD + r) * 4);
            #pragma unroll
            for (int q = 0; q < 4; q++)
                cpa4(sa + (uint32_t)(q * SPAD * 4), gp + q);
        }
        // E chunk [16 items][128 dims], contiguous: 16B copies
        for (int t = tid; t < TI * (EMB / 4); t += 256) {
            int i  = t >> 5;
            int dq = t & 31;
            const float* gp = &E[(size_t)(i0 + ic + i) * EMB + dq * 4];
            uint32_t sa = es_base + (uint32_t)(((b * TI + i) * SPAD + dq * 4) * 4);
            cpa16(sa, gp);
        }
        cpa_commit();
    };

    stage_async(0, 0);

    for (int cch = 0; cch < NCHUNK; cch++) {
        const int b = cch & 1;
        if (cch + 1 < NCHUNK) {
            stage_async((cch + 1) * TI, b ^ 1);  // overlaps compute below
            cpa_wait<1>();                        // buffer b resident
        } else {
            cpa_wait<0>();
        }
        __syncthreads();                          // all threads see buffer b

        float facc[8][8];
        #pragma unroll
        for (int r = 0; r < 8; r++)
            #pragma unroll
            for (int c = 0; c < 8; c++) facc[r][c] = 0.f;

        #pragma unroll
        for (int k = 0; k < TI; k++) {
            float4 xa = *reinterpret_cast<const float4*>(&xs[b][k][r0]);
            float4 xb = *reinterpret_cast<const float4*>(&xs[b][k][r0 + 4]);
            float4 ea = *reinterpret_cast<const float4*>(&Es[b][k][d0]);
            float4 eb = *reinterpret_cast<const float4*>(&Es[b][k][d0 + 4]);
            float xr[8] = {xa.x, xa.y, xa.z, xa.w, xb.x, xb.y, xb.z, xb.w};
            float ec[8] = {ea.x, ea.y, ea.z, ea.w, eb.x, eb.y, eb.z, eb.w};
            #pragma unroll
            for (int r = 0; r < 8; r++)
                #pragma unroll
                for (int c = 0; c < 8; c++)
                    facc[r][c] = fmaf(xr[r], ec[c], facc[r][c]);
        }
        #pragma unroll
        for (int r = 0; r < 8; r++)
            #pragma unroll
            for (int c = 0; c < 8; c++) gacc[r][c] += facc[r][c];

        __syncthreads();   // readers of b done before b is re-staged (iter cch+1)
    }

    float* part = &g_part[(size_t)blockIdx.y * BATCH * EMB];
    #pragma unroll
    for (int r = 0; r < 8; r++) {
        float* pp = &part[(size_t)(row0 + r0 + r) * EMB + d0];
        *reinterpret_cast<float4*>(pp) =
            make_float4(gacc[r][0], gacc[r][1], gacc[r][2], gacc[r][3]);
        *reinterpret_cast<float4*>(pp + 4) =
            make_float4(gacc[r][4], gacc[r][5], gacc[r][6], gacc[r][7]);
    }
}

// ---------------- kernel 1b: fold K-split partials in fp64 ----------------
__global__ __launch_bounds__(256) void k_reduce() {
    int i = blockIdx.x * blockDim.x + threadIdx.x;
    if (i < BATCH * EMB) {
        double sum = 0.0;
        for (int s = 0; s < SPLIT; s++) sum += (double)g_part[(size_t)s * BATCH * EMB + i];
        g_xemb[i] = (float)sum;
    }
}

// ---------------- kernel 2: scores = x_emb @ E^T (tf32 TC, bf16 output) --------
__global__ __launch_bounds__(256) void k_gemm2_tc(const float* __restrict__ E) {
    __shared__ uint32_t As[RTILE][APAD];
    __shared__ uint32_t Bs[JTILE][APAD];
    const int tid  = threadIdx.x;
    const int lane = tid & 31;
    const int warp = tid >> 5;
    const int row0 = blockIdx.y * RTILE;
    const int j0   = blockIdx.x * JTILE;
    const int g    = lane >> 2;
    const int c    = lane & 3;

    float cr[16][4];
    #pragma unroll
    for (int nt = 0; nt < 16; nt++)
        #pragma unroll
        for (int q = 0; q < 4; q++) cr[nt][q] = 0.f;

    for (int kc = 0; kc < EMB; kc += KCH) {
        __syncthreads();
        for (int t = tid; t < RTILE * (KCH / 4); t += 256) {
            int r  = t >> 3;
            int kq = t & 7;
            float4 v = *reinterpret_cast<const float4*>(
                &g_xemb[(size_t)(row0 + r) * EMB + kc + kq * 4]);
            uint4 u = make_uint4(f2tf32(v.x), f2tf32(v.y), f2tf32(v.z), f2tf32(v.w));
            *reinterpret_cast<uint4*>(&As[r][kq * 4]) = u;
        }
        for (int t = tid; t < JTILE * (KCH / 4); t += 256) {
            int r  = t >> 3;
            int kq = t & 7;
            int jj = j0 + r;
            if (jj >= NITEMS) jj = NITEMS - 1;
            float4 v = *reinterpret_cast<const float4*>(
                &E[(size_t)jj * EMB + kc + kq * 4]);
            uint4 u = make_uint4(f2tf32(v.x), f2tf32(v.y), f2tf32(v.z), f2tf32(v.w));
            *reinterpret_cast<uint4*>(&Bs[r][kq * 4]) = u;
        }
        __syncthreads();

        #pragma unroll
        for (int s = 0; s < KCH / 8; s++) {
            const int k0 = s * 8;
            uint32_t a0 = As[warp * 16 + g][k0 + c];
            uint32_t a1 = As[warp * 16 + 8 + g][k0 + c];
            uint32_t a2 = As[warp * 16 + g][k0 + c + 4];
            uint32_t a3 = As[warp * 16 + 8 + g][k0 + c + 4];
            #pragma unroll
            for (int nt = 0; nt < 16; nt++) {
                uint32_t b0 = Bs[nt * 8 + g][k0 + c];
                uint32_t b1 = Bs[nt * 8 + g][k0 + c + 4];
                mma_tf32(cr[nt], a0, a1, a2, a3, b0, b1);
            }
        }
    }

    #pragma unroll
    for (int nt = 0; nt < 16; nt++) {
        if (j0 + nt * 8 + 8 <= NITEMS) {
            int jz = j0 + nt * 8 + 2 * c;
            int r  = row0 + warp * 16 + g;
            __nv_bfloat162 p01 = make_bfloat162(__float2bfloat16_rn(cr[nt][0]),
                                                __float2bfloat16_rn(cr[nt][1]));
            __nv_bfloat162 p23 = make_bfloat162(__float2bfloat16_rn(cr[nt][2]),
                                                __float2bfloat16_rn(cr[nt][3]));
            *reinterpret_cast<__nv_bfloat162*>(&g_scores[(size_t)r * NITEMS + jz]) = p01;
            *reinterpret_cast<__nv_bfloat162*>(&g_scores[(size_t)(r + 8) * NITEMS + jz]) = p23;
        }
    }
}

// ---------------- kernel 3: sampled thresh + overflow-safe compact + fp64 -------
// UNCHANGED from the round-16 verified-correct version.
__device__ __forceinline__ unsigned ord16(unsigned h) {   // ordered bf16 (16-bit)
    return (h & 0x8000u) ? (0xffffu & ~h) : (h | 0x8000u);
}
__device__ __forceinline__ unsigned long long ordu64(double d) {
    unsigned long long u = __double_as_longlong(d);
    return (u & 0x8000000000000000ull) ? ~u : (u | 0x8000000000000000ull);
}

__global__ __launch_bounds__(256) void k_topk(const float* __restrict__ E,
                                              float* __restrict__ out) {
    __shared__ union {
        unsigned hist[4096];
        unsigned long long keys[CAND_MAX];
    } u;
    __shared__ unsigned cidx[CAND_MAX];
    __shared__ float xrow[EMB];
    __shared__ unsigned strip[256];
    __shared__ int s_bin, s_cnt;
    __shared__ unsigned long long wkey[8];
    __shared__ unsigned wbi[8];
    __shared__ int wpos[8];

    const int row = blockIdx.x;
    const int tid = threadIdx.x;
    const int lane = tid & 31;
    const int warp = tid >> 5;
    const uint4* s16 = reinterpret_cast<const uint4*>(&g_scores[(size_t)row * NITEMS]);

    if (tid < EMB) xrow[tid] = g_xemb[row * EMB + tid];
    for (int b = tid; b < 4096; b += 256) u.hist[b] = 0;
    __syncthreads();

    for (int i = tid; i < SAMPLE_U4; i += 256) {
        uint4 v = s16[i * 16];
        unsigned w[4] = {v.x, v.y, v.z, v.w};
        #pragma unroll
        for (int q = 0; q < 4; q++) {
            atomicAdd(&u.hist[ord16(w[q] & 0xffffu) >> 4], 1u);
            atomicAdd(&u.hist[ord16(w[q] >> 16) >> 4], 1u);
        }
    }
    __syncthreads();

    unsigned loc = 0;
    #pragma unroll
    for (int q = 0; q < 16; q++) loc += u.hist[tid * 16 + q];
    strip[tid] = loc;
    __syncthreads();
    if (tid == 0) {
        int acc = 0, bin = 0;
        for (int t = 255; t >= 0; t--) {
            if (acc + (int)strip[t] >= CAND_TARGET) {
                for (int b = t * 16 + 15; b >= t * 16; b--) {
                    if (acc + (int)u.hist[b] >= CAND_TARGET) { bin = b; break; }
                    acc += (int)u.hist[b];
                }
                break;
            }
            acc += (int)strip[t];
        }
        s_bin = bin;
    }
    __syncthreads();

    int bin = s_bin;
    int cnt;
    for (int attempt = 0; attempt < 16; attempt++) {
        if (tid == 0) s_cnt = 0;
        __syncthreads();
        const unsigned thresh = ((unsigned)bin) << 4;
        for (int i = tid; i < QHALF; i += 256) {
            uint4 va = s16[i];
            uint4 vb = s16[i + QHALF];
            unsigned w[8] = {va.x, va.y, va.z, va.w, vb.x, vb.y, vb.z, vb.w};
            #pragma unroll
            for (int q = 0; q < 8; q++) {
                int base = (q < 4) ? (8 * i + 2 * q) : (8 * (i + QHALF) + 2 * (q - 4));
                if (ord16(w[q] & 0xffffu) >= thresh) {
                    int p = atomicAdd(&s_cnt, 1);
                    if (p < CAND_MAX) cidx[p] = (unsigned)base;
                }
                if (ord16(w[q] >> 16) >= thresh) {
                    int p = atomicAdd(&s_cnt, 1);
                    if (p < CAND_MAX) cidx[p] = (unsigned)(base + 1);
                }
            }
        }
        __syncthreads();
        cnt = s_cnt;
        if (cnt <= CAND_MAX) break;
        if (bin >= 4095) break;
        bin++;
        __syncthreads();
    }
    if (cnt > CAND_MAX) cnt = CAND_MAX;

    if (cnt < TOPK) {   // fail-safe, unreachable on healthy data
        for (int i = tid; i < CAND_MAX; i += 256) cidx[i] = (unsigned)i;
        cnt = CAND_MAX;
        __syncthreads();
    }

    __syncthreads();   // hist reads done; safe to alias u.keys
    for (int c2 = warp; c2 < cnt; c2 += 8) {
        const unsigned j = cidx[c2];
        const float4* Ej4 = reinterpret_cast<const float4*>(&E[(size_t)j * EMB]);
        float4 ev = __ldg(&Ej4[lane]);
        float4 xv = *reinterpret_cast<const float4*>(&xrow[lane * 4]);
        double s = (double)xv.x * (double)ev.x + (double)xv.y * (double)ev.y
                 + (double)xv.z * (double)ev.z + (double)xv.w * (double)ev.w;
        #pragma unroll
        for (int off = 16; off; off >>= 1)
            s += __shfl_down_sync(0xffffffffu, s, off);
        if (lane == 0) u.keys[c2] = ordu64(s);
    }
    __syncthreads();

    for (int k = 0; k < TOPK; k++) {
        unsigned long long bk = 0; unsigned bi = 0xffffffffu; int bp = -1;
        for (int i = tid; i < cnt; i += 256) {
            unsigned long long kk = u.keys[i];
            unsigned ii = cidx[i];
            if (kk > bk || (kk == bk && ii < bi)) { bk = kk; bi = ii; bp = i; }
        }
        #pragma unroll
        for (int off = 16; off; off >>= 1) {
            unsigned long long ok = __shfl_down_sync(0xffffffffu, bk, off);
            unsigned oi = __shfl_down_sync(0xffffffffu, bi, off);
            int op = __shfl_down_sync(0xffffffffu, bp, off);
            if (ok > bk || (ok == bk && oi < bi)) { bk = ok; bi = oi; bp = op; }
        }
        if (lane == 0) { wkey[warp] = bk; wbi[warp] = bi; wpos[warp] = bp; }
        __syncthreads();
        if (tid == 0) {
            unsigned long long fb = 0; unsigned fi = 0xffffffffu; int fp = -1;
            #pragma unroll
            for (int w = 0; w < 8; w++)
                if (wkey[w] > fb || (wkey[w] == fb && wbi[w] < fi)) {
                    fb = wkey[w]; fi = wbi[w]; fp = wpos[w];
                }
            out[row * TOPK + k] = (float)fi;
            if (fp >= 0) u.keys[fp] = 0;
        }
        __syncthreads();
    }
}

// ---------------- launch ----------------
extern "C" void kernel_launch(void* const* d_in, const int* in_sizes, int n_in,
                              void* d_out, int out_size) {
    const float* a0 = (const float*)d_in[0];
    const float* a1 = (const float*)d_in[1];
    const bool first_is_x = (in_sizes[0] == BATCH * NITEMS) ||
                            (in_sizes[0] == BATCH * NITEMS * 4);
    const float* x = first_is_x ? a0 : a1;             // [1024, 100000]
    const float* E = first_is_x ? a1 : a0;             // [100000, 128]
    float* out = (float*)d_out;                        // [1024, 50] float32 indices

    k_gemm1<<<dim3(BATCH / RB, SPLIT), 256>>>(x, E);
    k_reduce<<<(BATCH * EMB + 255) / 256, 256>>>();
    k_gemm2_tc<<<dim3((NITEMS + JTILE - 1) / JTILE, BATCH / RTILE), 256>>>(E);
    k_topk<<<BATCH, 256>>>(E, out);
}